// round 14
// baseline (speedup 1.0000x reference)
#include <cuda_runtime.h>
#include <cstdint>

// Problem constants
#define HH 14
#define WWD 14
#define HW 196
#define CH 512
#define NCHAIN 8     // 4 modes x 2 batches
#define CLUS 8       // CTAs per cluster (one chain)
#define NTHR 512

// Dynamic smem layout (bytes)
#define OFF_AOWN  0                      // 25 x 512 x 4 = 51200 (owned-pixel a)
#define OFF_HACC  51200                  // 25 x 512 x 4 = 51200 (owned-pixel accum)
#define OFF_GBUF  102400                 // 4 x 512 x 4  = 8192  (rolling G)
#define OFF_SCR   110592                 // 3 x 512 x 4  = 6144  (JIT pool outputs)
#define OFF_HVEC  116736                 // 512 x 4      = 2048
#define OFF_ASMEM 118784                 // 2 x 512 x 4  = 4096  (a[t] ping-pong)
#define SMEM_SZ   122880

// Static device scratch
__device__ float g_A0[2 * HW * CH];           // Wx@input + b_in, [q][c]
__device__ float g_Hv[NCHAIN * HW * CH];      // h history for epilogue
__device__ float g_Hship[NCHAIN * 2 * CH];    // hacc ship, double buffered

__device__ __forceinline__ float4 relu4(float4 a) {
    return make_float4(fmaxf(a.x, 0.f), fmaxf(a.y, 0.f),
                       fmaxf(a.z, 0.f), fmaxf(a.w, 0.f));
}
__device__ __forceinline__ float4 add4(float4 a, float4 b) {
    return make_float4(a.x + b.x, a.y + b.y, a.z + b.z, a.w + b.w);
}
__device__ __forceinline__ float max4(float4 a) {
    return fmaxf(fmaxf(a.x, a.y), fmaxf(a.z, a.w));
}
__device__ __forceinline__ float sum4(float4 a) {
    return (a.x + a.y) + (a.z + a.w);
}
__device__ __forceinline__ float dot4(float4 a, float4 b) {
    return a.x * b.x + a.y * b.y + a.z * b.z + a.w * b.w;
}
__device__ __forceinline__ float4 exp4(float4 a, float m) {
    return make_float4(__expf(a.x - m), __expf(a.y - m),
                       __expf(a.z - m), __expf(a.w - m));
}
__device__ __forceinline__ float warp_max(float v) {
#pragma unroll
    for (int o = 16; o; o >>= 1)
        v = fmaxf(v, __shfl_xor_sync(0xffffffffu, v, o));
    return v;
}
// Warp max for NON-NEGATIVE floats: IEEE bits monotone for v >= 0.
__device__ __forceinline__ float warp_max_pos(float v) {
    uint32_t r;
    asm("redux.sync.max.u32 %0, %1, 0xffffffff;" : "=r"(r) : "r"(__float_as_uint(v)));
    return __uint_as_float(r);
}
__device__ __forceinline__ float warp_sum(float v) {
#pragma unroll
    for (int o = 16; o; o >>= 1)
        v += __shfl_xor_sync(0xffffffffu, v, o);
    return v;
}
__device__ __forceinline__ uint32_t s2u(const void* p) {
    uint32_t a;
    asm("{ .reg .u64 t; cvta.to.shared.u64 t, %1; cvt.u32.u64 %0, t; }"
        : "=r"(a) : "l"(p));
    return a;
}
__device__ __forceinline__ void st_cluster_f32(uint32_t laddr, uint32_t rnk, float v) {
    uint32_t ra;
    asm("mapa.shared::cluster.u32 %0, %1, %2;" : "=r"(ra) : "r"(laddr), "r"(rnk));
    asm volatile("st.shared::cluster.f32 [%0], %1;" :: "r"(ra), "f"(v) : "memory");
}
#define CLUSTER_ARRIVE() asm volatile("barrier.cluster.arrive.aligned;" ::: "memory")
#define CLUSTER_WAIT()   asm volatile("barrier.cluster.wait.aligned;"   ::: "memory")

struct C4 { float4 v0, v1, v2, v3; };

// Softmax-pool of one cell: whole warp = 512 channels, 16/lane.
// g4 == nullptr means G == 0 (the cell's own step).
__device__ __forceinline__ C4 pool_cell(const float4* a4, const float4* g4, int lane) {
    float4 z0, z1, z2, z3;
    if (g4) {
        z0 = relu4(add4(a4[lane],      g4[lane]));
        z1 = relu4(add4(a4[lane + 32], g4[lane + 32]));
        z2 = relu4(add4(a4[lane + 64], g4[lane + 64]));
        z3 = relu4(add4(a4[lane + 96], g4[lane + 96]));
    } else {
        z0 = relu4(a4[lane]);      z1 = relu4(a4[lane + 32]);
        z2 = relu4(a4[lane + 64]); z3 = relu4(a4[lane + 96]);
    }
    float m = warp_max_pos(fmaxf(fmaxf(max4(z0), max4(z1)),
                                 fmaxf(max4(z2), max4(z3))));
    float4 e0 = exp4(z0, m), e1 = exp4(z1, m);
    float4 e2 = exp4(z2, m), e3 = exp4(z3, m);
    float es = warp_sum(sum4(e0) + sum4(e1) + sum4(e2) + sum4(e3));
    float inv = __fdividef(1.f, es);
    C4 r;
    r.v0 = make_float4(z0.x * e0.x * inv, z0.y * e0.y * inv, z0.z * e0.z * inv, z0.w * e0.w * inv);
    r.v1 = make_float4(z1.x * e1.x * inv, z1.y * e1.y * inv, z1.z * e1.z * inv, z1.w * e1.w * inv);
    r.v2 = make_float4(z2.x * e2.x * inv, z2.y * e2.y * inv, z2.z * e2.z * inv, z2.w * e2.w * inv);
    r.v3 = make_float4(z3.x * e3.x * inv, z3.y * e3.y * inv, z3.z * e3.z * inv, z3.w * e3.w * inv);
    return r;
}

// ---------------------------------------------------------------------------
// Prologue: A0[q][c] = sum_k Wx[c,k]*input[b,k,p] + b_in[c]
// Warp-row GEMV: lanes cover k (coalesced weight reads), butterfly reduce.
// ---------------------------------------------------------------------------
__global__ __launch_bounds__(NTHR) void prologue_kernel(
    const float* __restrict__ input, const float* __restrict__ Wx,
    const float* __restrict__ b_in) {
    __shared__ float xs[4 * 520];
    __shared__ float os[4 * 512];
    const int tid = threadIdx.x;
    const int wid = tid >> 5, lane = tid & 31;
    const int b   = blockIdx.x / 49;
    const int p0  = (blockIdx.x % 49) * 4;
    {
        float4 v = *(const float4*)(input + (size_t)(b * CH + tid) * HW + p0);
        xs[0 * 520 + tid] = v.x; xs[1 * 520 + tid] = v.y;
        xs[2 * 520 + tid] = v.z; xs[3 * 520 + tid] = v.w;
    }
    __syncthreads();

    float4 xv[4][4];
#pragma unroll
    for (int j = 0; j < 4; j++)
#pragma unroll
        for (int kk = 0; kk < 4; kk++)
            xv[j][kk] = *(const float4*)(xs + j * 520 + 4 * lane + 128 * kk);

    for (int g = 0; g < 16; g++) {
        const int r0 = wid * 32 + g * 2;
        float4 w0[4], w1[4];
#pragma unroll
        for (int kk = 0; kk < 4; kk++) {
            w0[kk] = *(const float4*)(Wx + (size_t)r0 * CH + 4 * lane + 128 * kk);
            w1[kk] = *(const float4*)(Wx + (size_t)(r0 + 1) * CH + 4 * lane + 128 * kk);
        }
        float d0[4], d1[4];
#pragma unroll
        for (int j = 0; j < 4; j++) {
            float s0 = 0.f, s1 = 0.f;
#pragma unroll
            for (int kk = 0; kk < 4; kk++) {
                s0 += dot4(w0[kk], xv[j][kk]);
                s1 += dot4(w1[kk], xv[j][kk]);
            }
            d0[j] = warp_sum(s0);
            d1[j] = warp_sum(s1);
        }
        if (lane < 8) {
            int rr = lane >> 2, j = lane & 3;
            os[j * 512 + r0 + rr] = rr ? d1[j] : d0[j];
        }
    }
    __syncthreads();
    float bb = b_in[tid];
#pragma unroll
    for (int j = 0; j < 4; j++)
        g_A0[(size_t)(b * HW + p0 + j) * CH + tid] = os[j * 512 + tid] + bb;
}

// ---------------------------------------------------------------------------
// Scan: 8-CTA cluster per chain, 196 steps, 1 barrier round + 2 syncs/step.
// RETIMED: cell c scatters at step c+2 (PRE-wait, overlapping barrier+skew);
// JIT pools for cells t and t-2 also pre-wait. Only cell t-1's pool (needs
// gbuf[t-1], acquired by this step's wait) + assemble + matvec are post-wait.
// ---------------------------------------------------------------------------
__global__ void __cluster_dims__(CLUS, 1, 1) __launch_bounds__(NTHR, 1)
scan_kernel(const float* __restrict__ Wh) {
    extern __shared__ char smem[];
    const uint32_t sbase = s2u(smem);
    float* aown  = (float*)(smem + OFF_AOWN);
    float* hacc  = (float*)(smem + OFF_HACC);
    float* gbuf  = (float*)(smem + OFF_GBUF);
    float* scr   = (float*)(smem + OFF_SCR);
    float* hvec  = (float*)(smem + OFF_HVEC);
    float* asmem = (float*)(smem + OFF_ASMEM);

    const int tid  = threadIdx.x;
    const int wid  = tid >> 5, lane = tid & 31;
    const int rank = blockIdx.x & 7;
    const int chain = blockIdx.x >> 3;
    const int mode = chain >> 1, bb = chain & 1;

    // Matvec rows R..R+3 per warp; lane holds channels 4*lane + 128*k
    const int R = 64 * rank + 4 * wid;
    float4 wreg[4][4];
#pragma unroll
    for (int i = 0; i < 4; i++)
#pragma unroll
        for (int k = 0; k < 4; k++)
            wreg[i][k] = *(const float4*)(Wh + (size_t)(R + i) * CH + 4 * lane + 128 * k);

    const float* Ab = g_A0 + (size_t)bb * HW * CH;
    float* Hc   = g_Hv + (size_t)chain * HW * CH;
    float* ship = g_Hship + (size_t)chain * 2 * CH;

    // Load owned-pixel a vectors (pixels q: q&7==rank, slot q>>3), zero hacc.
    const int nown = (rank < 4) ? 25 : 24;
    for (int i = 0; i < nown; i++) {
        int q = rank + 8 * i;
        int qx = q / WWD, qy = q - qx * WWD;
        int fx = (mode & 2) ? (HH - 1 - qx) : qx;
        int fy = (mode & 1) ? (WWD - 1 - qy) : qy;
        aown[i * CH + tid] = __ldg(Ab + (size_t)(fx * WWD + fy) * CH + tid);
        hacc[i * CH + tid] = 0.f;
    }
    {   // a(0) -> asmem buf 0
        int fx = (mode & 2) ? (HH - 1) : 0;
        int fy = (mode & 1) ? (WWD - 1) : 0;
        asmem[tid] = __ldg(Ab + (size_t)(fx * WWD + fy) * CH + tid);
    }
    __syncthreads();

    for (int t = 0; t < HW; t++) {
        const int py = t % WWD;
        const int par = t & 1;
        const float4* a4 = (const float4*)(asmem + par * CH);

        // ---------- PRE-WAIT (overlaps peers' tails + barrier round) ----------
        if (wid == 0) {
            // cell t (G = 0)
            C4 r = pool_cell(a4, nullptr, lane);
            float4* s = (float4*)scr;
            s[lane] = r.v0; s[lane + 32] = r.v1;
            s[lane + 64] = r.v2; s[lane + 96] = r.v3;
        } else if (wid == 2) {
            // cell t-2 (gbuf[t-2] visible since wait(t-1))
            float4* s = (float4*)(scr + 2 * CH);
            if (py >= 2) {
                C4 r = pool_cell(a4, (const float4*)(gbuf + ((t - 2) & 3) * CH), lane);
                s[lane] = r.v0; s[lane + 32] = r.v1;
                s[lane + 64] = r.v2; s[lane + 96] = r.v3;
            } else {
                float4 z = make_float4(0.f, 0.f, 0.f, 0.f);
                s[lane] = z; s[lane + 32] = z; s[lane + 64] = z; s[lane + 96] = z;
            }
        } else if (wid >= 3 && t >= 2) {
            // eager scatter of cell c = t-2 into owned future pixels q >= t+1
            const int c = t - 2, cx = c / WWD, cy = c - cx * WWD;
            const float4* g4 = (const float4*)(gbuf + ((t - 2) & 3) * CH);
            for (int i = wid - 3; i < 25; i += 13) {
                int q = rank + 8 * i;
                if (q >= HW) break;
                if (q < t + 1) continue;
                int qx = q / WWD, qy = q - qx * WWD;
                if (qx < cx || qy < cy) continue;
                const float4* aq = (const float4*)(aown + i * CH);
                C4 r = pool_cell(aq, g4, lane);
                float4* hc = (float4*)(hacc + i * CH);
                hc[lane]      = add4(hc[lane], r.v0);
                hc[lane + 32] = add4(hc[lane + 32], r.v1);
                hc[lane + 64] = add4(hc[lane + 64], r.v2);
                hc[lane + 96] = add4(hc[lane + 96], r.v3);
            }
        }

        // prefetch a(t+1)
        if (t + 1 < HW) {
            int pn = t + 1, pxn = pn / WWD, pyn = pn - pxn * WWD;
            int fx = (mode & 2) ? (HH - 1 - pxn) : pxn;
            int fy = (mode & 1) ? (WWD - 1 - pyn) : pyn;
            asmem[(par ^ 1) * CH + tid] = __ldg(Ab + (size_t)(fx * WWD + fy) * CH + tid);
        }

        if (t > 0) CLUSTER_WAIT();   // acquires gbuf[t-1] + ship(pixel t)

        // ---------- POST-WAIT (short chain) ----------
        float hrecv = (t > 0) ? __ldcg(ship + par * CH + tid) : 0.f;
        if (wid == 1) {
            // cell t-1 (gbuf[t-1] just acquired)
            float4* s = (float4*)(scr + CH);
            if (py >= 1) {
                C4 r = pool_cell(a4, (const float4*)(gbuf + ((t - 1) & 3) * CH), lane);
                s[lane] = r.v0; s[lane + 32] = r.v1;
                s[lane + 64] = r.v2; s[lane + 96] = r.v3;
            } else {
                float4 z = make_float4(0.f, 0.f, 0.f, 0.f);
                s[lane] = z; s[lane + 32] = z; s[lane + 64] = z; s[lane + 96] = z;
            }
        }
        __syncthreads();   // S1: scr + this step's hacc scatter complete

        // Ship hacc[t+1] (cells <= t-2 now included: scatter@t added cell t-2)
        if (t + 1 < HW && rank == ((t + 1) & 7))
            ship[((t + 1) & 1) * CH + tid] = hacc[((t + 1) >> 3) * CH + tid];

        // assemble h(t), replicated
        float h = hrecv + scr[tid] + scr[CH + tid] + scr[2 * CH + tid];
        hvec[tid] = h;
        if (rank == (t & 7)) Hc[(size_t)t * CH + tid] = h;
        __syncthreads();   // S2: hvec ready

        // matvec: my 64 rows of G(t) = Wh rows . h(t); all-gather into gbuf[t&3]
        {
            const float4* hv4 = (const float4*)hvec;
            float4 h0 = hv4[lane],      h1 = hv4[lane + 32];
            float4 h2 = hv4[lane + 64], h3 = hv4[lane + 96];
            float v0 = warp_sum(dot4(wreg[0][0], h0) + dot4(wreg[0][1], h1) +
                                dot4(wreg[0][2], h2) + dot4(wreg[0][3], h3));
            float v1 = warp_sum(dot4(wreg[1][0], h0) + dot4(wreg[1][1], h1) +
                                dot4(wreg[1][2], h2) + dot4(wreg[1][3], h3));
            float v2 = warp_sum(dot4(wreg[2][0], h0) + dot4(wreg[2][1], h1) +
                                dot4(wreg[2][2], h2) + dot4(wreg[2][3], h3));
            float v3 = warp_sum(dot4(wreg[3][0], h0) + dot4(wreg[3][1], h1) +
                                dot4(wreg[3][2], h2) + dot4(wreg[3][3], h3));
            if (lane < 4) {
                float sv = (lane == 0) ? v0 : (lane == 1) ? v1 : (lane == 2) ? v2 : v3;
                uint32_t la = sbase + OFF_GBUF +
                              (uint32_t)(((t & 3) * CH + R + lane) * 4);
#pragma unroll
                for (int d = 0; d < 8; d++) st_cluster_f32(la, (uint32_t)d, sv);
            }
        }
        CLUSTER_ARRIVE();   // release: gbuf rows + ship
    }
    CLUSTER_WAIT();         // close final generation
}

// ---------------------------------------------------------------------------
// Fused epilogue: Y = Wo @ (sum_m Hv) + 4*b_out, then channel softmax -> out
// ---------------------------------------------------------------------------
__global__ __launch_bounds__(NTHR) void epilogue_kernel(
    const float* __restrict__ Wo, const float* __restrict__ b_out,
    float* __restrict__ out) {
    __shared__ float hs[4 * 520];
    __shared__ float os[4 * 512];
    __shared__ float red[16];
    const int tid = threadIdx.x;
    const int wid = tid >> 5, lane = tid & 31;
    const int b   = blockIdx.x / 49;
    const int p0  = (blockIdx.x % 49) * 4;
#pragma unroll
    for (int j = 0; j < 4; j++) {
        float s0 = g_Hv[((size_t)(0 + b) * HW + p0 + j) * CH + tid];
        float s1 = g_Hv[((size_t)(2 + b) * HW + p0 + j) * CH + tid];
        float s2 = g_Hv[((size_t)(4 + b) * HW + p0 + j) * CH + tid];
        float s3 = g_Hv[((size_t)(6 + b) * HW + p0 + j) * CH + tid];
        hs[j * 520 + tid] = (s0 + s1) + (s2 + s3);
    }
    __syncthreads();

    float4 xv[4][4];
#pragma unroll
    for (int j = 0; j < 4; j++)
#pragma unroll
        for (int kk = 0; kk < 4; kk++)
            xv[j][kk] = *(const float4*)(hs + j * 520 + 4 * lane + 128 * kk);

    for (int g = 0; g < 16; g++) {
        const int r0 = wid * 32 + g * 2;
        float4 w0[4], w1[4];
#pragma unroll
        for (int kk = 0; kk < 4; kk++) {
            w0[kk] = *(const float4*)(Wo + (size_t)r0 * CH + 4 * lane + 128 * kk);
            w1[kk] = *(const float4*)(Wo + (size_t)(r0 + 1) * CH + 4 * lane + 128 * kk);
        }
        float d0[4], d1[4];
#pragma unroll
        for (int j = 0; j < 4; j++) {
            float s0 = 0.f, s1 = 0.f;
#pragma unroll
            for (int kk = 0; kk < 4; kk++) {
                s0 += dot4(w0[kk], xv[j][kk]);
                s1 += dot4(w1[kk], xv[j][kk]);
            }
            d0[j] = warp_sum(s0);
            d1[j] = warp_sum(s1);
        }
        if (lane < 8) {
            int rr = lane >> 2, j = lane & 3;
            os[j * 512 + r0 + rr] = rr ? d1[j] : d0[j];
        }
    }
    __syncthreads();

    float bo = 4.f * b_out[tid];
#pragma unroll
    for (int j = 0; j < 4; j++) {
        float acc = os[j * 512 + tid] + bo;
        float m = warp_max(acc);
        if (lane == 0) red[wid] = m;
        __syncthreads();
        float mm = red[0];
#pragma unroll
        for (int k = 1; k < 16; k++) mm = fmaxf(mm, red[k]);
        float e = __expf(acc - mm);
        __syncthreads();
        float s = warp_sum(e);
        if (lane == 0) red[wid] = s;
        __syncthreads();
        float ss = 0.f;
#pragma unroll
        for (int k = 0; k < 16; k++) ss += red[k];
        out[((size_t)b * CH + tid) * HW + p0 + j] = e / ss;
        __syncthreads();
    }
}

extern "C" void kernel_launch(void* const* d_in, const int* in_sizes, int n_in,
                              void* d_out, int out_size) {
    const float* input = (const float*)d_in[0];
    const float* Wx    = (const float*)d_in[1];
    const float* Wh    = (const float*)d_in[2];
    const float* b_in  = (const float*)d_in[3];
    const float* Wo    = (const float*)d_in[4];
    const float* b_out = (const float*)d_in[5];
    float* out = (float*)d_out;
    (void)in_sizes; (void)n_in; (void)out_size;

    cudaFuncSetAttribute(scan_kernel,
                         cudaFuncAttributeMaxDynamicSharedMemorySize, SMEM_SZ);

    prologue_kernel<<<98, NTHR>>>(input, Wx, b_in);
    scan_kernel<<<NCHAIN * CLUS, NTHR, SMEM_SZ>>>(Wh);
    epilogue_kernel<<<98, NTHR>>>(Wo, b_out, out);
}

// round 16
// speedup vs baseline: 1.1759x; 1.1759x over previous
#include <cuda_runtime.h>
#include <cstdint>

// Problem constants
#define HH 14
#define WWD 14
#define HW 196
#define CH 512
#define NCHAIN 8     // 4 modes x 2 batches
#define CLUS 8       // CTAs per cluster (one chain)
#define NTHR 512

// Dynamic smem layout (bytes)
#define OFF_AOWN  0                      // 25 x 512 x 4 = 51200 (owned-pixel a)
#define OFF_HACC  51200                  // 25 x 512 x 4 = 51200 (owned-pixel accum)
#define OFF_GBUF  102400                 // 4 x 512 x 4  = 8192  (rolling G)
#define OFF_SCR   110592                 // 3 x 512 x 4  = 6144  (JIT pool outputs)
#define OFF_HVEC  116736                 // 512 x 4      = 2048
#define OFF_ASMEM 118784                 // 2 x 512 x 4  = 4096  (a[t] ping-pong)
#define SMEM_SZ   122880

// Static device scratch
__device__ float g_A0[2 * HW * CH];           // Wx@input + b_in, [q][c]
__device__ float g_Hv[NCHAIN * HW * CH];      // h history for epilogue
__device__ float g_Hship[NCHAIN * 2 * CH];    // hacc ship, double buffered

__device__ __forceinline__ float4 relu4(float4 a) {
    return make_float4(fmaxf(a.x, 0.f), fmaxf(a.y, 0.f),
                       fmaxf(a.z, 0.f), fmaxf(a.w, 0.f));
}
__device__ __forceinline__ float4 add4(float4 a, float4 b) {
    return make_float4(a.x + b.x, a.y + b.y, a.z + b.z, a.w + b.w);
}
__device__ __forceinline__ float max4(float4 a) {
    return fmaxf(fmaxf(a.x, a.y), fmaxf(a.z, a.w));
}
__device__ __forceinline__ float sum4(float4 a) {
    return (a.x + a.y) + (a.z + a.w);
}
__device__ __forceinline__ float dot4(float4 a, float4 b) {
    return a.x * b.x + a.y * b.y + a.z * b.z + a.w * b.w;
}
__device__ __forceinline__ float4 exp4(float4 a, float m) {
    return make_float4(__expf(a.x - m), __expf(a.y - m),
                       __expf(a.z - m), __expf(a.w - m));
}
__device__ __forceinline__ float warp_max(float v) {
#pragma unroll
    for (int o = 16; o; o >>= 1)
        v = fmaxf(v, __shfl_xor_sync(0xffffffffu, v, o));
    return v;
}
// Warp max for NON-NEGATIVE floats: IEEE bits monotone for v >= 0.
__device__ __forceinline__ float warp_max_pos(float v) {
    uint32_t r;
    asm("redux.sync.max.u32 %0, %1, 0xffffffff;" : "=r"(r) : "r"(__float_as_uint(v)));
    return __uint_as_float(r);
}
__device__ __forceinline__ float warp_sum(float v) {
#pragma unroll
    for (int o = 16; o; o >>= 1)
        v += __shfl_xor_sync(0xffffffffu, v, o);
    return v;
}
__device__ __forceinline__ uint32_t s2u(const void* p) {
    uint32_t a;
    asm("{ .reg .u64 t; cvta.to.shared.u64 t, %1; cvt.u32.u64 %0, t; }"
        : "=r"(a) : "l"(p));
    return a;
}
__device__ __forceinline__ void st_cluster_f32(uint32_t laddr, uint32_t rnk, float v) {
    uint32_t ra;
    asm("mapa.shared::cluster.u32 %0, %1, %2;" : "=r"(ra) : "r"(laddr), "r"(rnk));
    asm volatile("st.shared::cluster.f32 [%0], %1;" :: "r"(ra), "f"(v) : "memory");
}
__device__ __forceinline__ void st_cluster_u64(uint32_t laddr, uint32_t rnk,
                                               unsigned long long v) {
    uint32_t ra;
    asm("mapa.shared::cluster.u32 %0, %1, %2;" : "=r"(ra) : "r"(laddr), "r"(rnk));
    asm volatile("st.shared::cluster.u64 [%0], %1;" :: "r"(ra), "l"(v) : "memory");
}
// Packed f32x2 helpers (sm_103a)
__device__ __forceinline__ unsigned long long pack2(float x, float y) {
    unsigned long long r;
    asm("mov.b64 %0, {%1, %2};" : "=l"(r) : "f"(x), "f"(y));
    return r;
}
__device__ __forceinline__ unsigned long long fma2(unsigned long long a,
                                                   unsigned long long b,
                                                   unsigned long long c) {
    unsigned long long d;
    asm("fma.rn.f32x2 %0, %1, %2, %3;" : "=l"(d) : "l"(a), "l"(b), "l"(c));
    return d;
}
__device__ __forceinline__ float unpack_sum(unsigned long long a) {
    float lo, hi;
    asm("mov.b64 {%0, %1}, %2;" : "=f"(lo), "=f"(hi) : "l"(a));
    return lo + hi;
}
#define CLUSTER_ARRIVE() asm volatile("barrier.cluster.arrive.aligned;" ::: "memory")
#define CLUSTER_WAIT()   asm volatile("barrier.cluster.wait.aligned;"   ::: "memory")

struct C4 { float4 v0, v1, v2, v3; };

// Softmax-pool of one cell: whole warp = 512 channels, 16/lane.
// g4 == nullptr means G == 0 (the cell's own step).
__device__ __forceinline__ C4 pool_cell(const float4* a4, const float4* g4, int lane) {
    float4 z0, z1, z2, z3;
    if (g4) {
        z0 = relu4(add4(a4[lane],      g4[lane]));
        z1 = relu4(add4(a4[lane + 32], g4[lane + 32]));
        z2 = relu4(add4(a4[lane + 64], g4[lane + 64]));
        z3 = relu4(add4(a4[lane + 96], g4[lane + 96]));
    } else {
        z0 = relu4(a4[lane]);      z1 = relu4(a4[lane + 32]);
        z2 = relu4(a4[lane + 64]); z3 = relu4(a4[lane + 96]);
    }
    float m = warp_max_pos(fmaxf(fmaxf(max4(z0), max4(z1)),
                                 fmaxf(max4(z2), max4(z3))));
    float4 e0 = exp4(z0, m), e1 = exp4(z1, m);
    float4 e2 = exp4(z2, m), e3 = exp4(z3, m);
    float es = warp_sum(sum4(e0) + sum4(e1) + sum4(e2) + sum4(e3));
    float inv = __fdividef(1.f, es);
    C4 r;
    r.v0 = make_float4(z0.x * e0.x * inv, z0.y * e0.y * inv, z0.z * e0.z * inv, z0.w * e0.w * inv);
    r.v1 = make_float4(z1.x * e1.x * inv, z1.y * e1.y * inv, z1.z * e1.z * inv, z1.w * e1.w * inv);
    r.v2 = make_float4(z2.x * e2.x * inv, z2.y * e2.y * inv, z2.z * e2.z * inv, z2.w * e2.w * inv);
    r.v3 = make_float4(z3.x * e3.x * inv, z3.y * e3.y * inv, z3.z * e3.z * inv, z3.w * e3.w * inv);
    return r;
}

// ---------------------------------------------------------------------------
// Prologue: A0[q][c] = sum_k Wx[c,k]*input[b,k,p] + b_in[c]
// Warp-row GEMV: lanes cover k (coalesced weight reads), butterfly reduce.
// ---------------------------------------------------------------------------
__global__ __launch_bounds__(NTHR) void prologue_kernel(
    const float* __restrict__ input, const float* __restrict__ Wx,
    const float* __restrict__ b_in) {
    __shared__ float xs[4 * 520];
    __shared__ float os[4 * 512];
    const int tid = threadIdx.x;
    const int wid = tid >> 5, lane = tid & 31;
    const int b   = blockIdx.x / 49;
    const int p0  = (blockIdx.x % 49) * 4;
    {
        float4 v = *(const float4*)(input + (size_t)(b * CH + tid) * HW + p0);
        xs[0 * 520 + tid] = v.x; xs[1 * 520 + tid] = v.y;
        xs[2 * 520 + tid] = v.z; xs[3 * 520 + tid] = v.w;
    }
    __syncthreads();

    float4 xv[4][4];
#pragma unroll
    for (int j = 0; j < 4; j++)
#pragma unroll
        for (int kk = 0; kk < 4; kk++)
            xv[j][kk] = *(const float4*)(xs + j * 520 + 4 * lane + 128 * kk);

    for (int g = 0; g < 16; g++) {
        const int r0 = wid * 32 + g * 2;
        float4 w0[4], w1[4];
#pragma unroll
        for (int kk = 0; kk < 4; kk++) {
            w0[kk] = *(const float4*)(Wx + (size_t)r0 * CH + 4 * lane + 128 * kk);
            w1[kk] = *(const float4*)(Wx + (size_t)(r0 + 1) * CH + 4 * lane + 128 * kk);
        }
        float d0[4], d1[4];
#pragma unroll
        for (int j = 0; j < 4; j++) {
            float s0 = 0.f, s1 = 0.f;
#pragma unroll
            for (int kk = 0; kk < 4; kk++) {
                s0 += dot4(w0[kk], xv[j][kk]);
                s1 += dot4(w1[kk], xv[j][kk]);
            }
            d0[j] = warp_sum(s0);
            d1[j] = warp_sum(s1);
        }
        if (lane < 8) {
            int rr = lane >> 2, j = lane & 3;
            os[j * 512 + r0 + rr] = rr ? d1[j] : d0[j];
        }
    }
    __syncthreads();
    float bb = b_in[tid];
#pragma unroll
    for (int j = 0; j < 4; j++)
        g_A0[(size_t)(b * HW + p0 + j) * CH + tid] = os[j * 512 + tid] + bb;
}

// ---------------------------------------------------------------------------
// Scan: 8-CTA cluster per chain, 196 steps, 1 barrier round + 2 syncs/step.
// R13 schedule (wait at top). Packed-f32x2 matvec; 64-bit DSMEM scatter.
// ---------------------------------------------------------------------------
__global__ void __cluster_dims__(CLUS, 1, 1) __launch_bounds__(NTHR, 1)
scan_kernel(const float* __restrict__ Wh) {
    extern __shared__ char smem[];
    const uint32_t sbase = s2u(smem);
    float* aown  = (float*)(smem + OFF_AOWN);
    float* hacc  = (float*)(smem + OFF_HACC);
    float* gbuf  = (float*)(smem + OFF_GBUF);
    float* scr   = (float*)(smem + OFF_SCR);
    float* hvec  = (float*)(smem + OFF_HVEC);
    float* asmem = (float*)(smem + OFF_ASMEM);

    const int tid  = threadIdx.x;
    const int wid  = tid >> 5, lane = tid & 31;
    const int rank = blockIdx.x & 7;
    const int chain = blockIdx.x >> 3;
    const int mode = chain >> 1, bb = chain & 1;

    // Matvec rows R..R+3 per warp; lane holds channels 4*lane + 128*k.
    // Weights packed as f32x2 pairs: wp[i][2k..2k+1] covers float4 k of row R+i.
    const int R = 64 * rank + 4 * wid;
    unsigned long long wp[4][8];
#pragma unroll
    for (int i = 0; i < 4; i++)
#pragma unroll
        for (int k = 0; k < 4; k++) {
            float4 w = *(const float4*)(Wh + (size_t)(R + i) * CH + 4 * lane + 128 * k);
            wp[i][2 * k]     = pack2(w.x, w.y);
            wp[i][2 * k + 1] = pack2(w.z, w.w);
        }

    const float* Ab = g_A0 + (size_t)bb * HW * CH;
    float* Hc   = g_Hv + (size_t)chain * HW * CH;
    float* ship = g_Hship + (size_t)chain * 2 * CH;

    // Load owned-pixel a vectors (pixels q: q&7==rank, slot q>>3), zero hacc.
    const int nown = (rank < 4) ? 25 : 24;
    for (int i = 0; i < nown; i++) {
        int q = rank + 8 * i;
        int qx = q / WWD, qy = q - qx * WWD;
        int fx = (mode & 2) ? (HH - 1 - qx) : qx;
        int fy = (mode & 1) ? (WWD - 1 - qy) : qy;
        aown[i * CH + tid] = __ldg(Ab + (size_t)(fx * WWD + fy) * CH + tid);
        hacc[i * CH + tid] = 0.f;
    }
    {   // a(0) -> asmem buf 0
        int fx = (mode & 2) ? (HH - 1) : 0;
        int fy = (mode & 1) ? (WWD - 1) : 0;
        asmem[tid] = __ldg(Ab + (size_t)(fx * WWD + fy) * CH + tid);
    }
    __syncthreads();

    for (int t = 0; t < HW; t++) {
        const int py = t % WWD;
        const int par = t & 1;

        if (t > 0) CLUSTER_WAIT();   // gbuf[t-1] + ship(pixel t) visible

        // hacc ship of pixel t (cells <= t-3), sent by owner at step t-1
        float hrecv = (t > 0) ? __ldcg(ship + par * CH + tid) : 0.f;

        // Ship hacc[t+1] (cells <= t-2 complete; this step's scatter targets >= t+2)
        if (t + 1 < HW && rank == ((t + 1) & 7))
            ship[((t + 1) & 1) * CH + tid] = hacc[((t + 1) >> 3) * CH + tid];

        const float4* a4 = (const float4*)(asmem + par * CH);
        if (wid < 3) {
            // JIT pools: w0 -> cell t (G=0); w1 -> cell t-1 (py>=1); w2 -> cell t-2 (py>=2)
            float4* myscr = (float4*)(scr + wid * CH);
            bool active = (wid == 0) || (wid == 1 && py >= 1) || (wid == 2 && py >= 2);
            if (active) {
                const float4* g4 = nullptr;
                if (wid > 0) g4 = (const float4*)(gbuf + ((t - wid) & 3) * CH);
                C4 r = pool_cell(a4, g4, lane);
                myscr[lane] = r.v0; myscr[lane + 32] = r.v1;
                myscr[lane + 64] = r.v2; myscr[lane + 96] = r.v3;
            } else {
                float4 z = make_float4(0.f, 0.f, 0.f, 0.f);
                myscr[lane] = z; myscr[lane + 32] = z;
                myscr[lane + 64] = z; myscr[lane + 96] = z;
            }
        } else if (t >= 1) {
            // Eager scatter of cell c = t-1 to owned future pixels q >= t+2
            const int c = t - 1, cx = c / WWD, cy = c - cx * WWD;
            const float4* g4 = (const float4*)(gbuf + ((t - 1) & 3) * CH);
            for (int i = wid - 3; i < 25; i += 13) {
                int q = rank + 8 * i;
                if (q >= HW) break;
                if (q < t + 2) continue;
                int qx = q / WWD, qy = q - qx * WWD;
                if (qx < cx || qy < cy) continue;
                const float4* aq = (const float4*)(aown + i * CH);
                C4 r = pool_cell(aq, g4, lane);
                float4* hc = (float4*)(hacc + i * CH);
                hc[lane]      = add4(hc[lane], r.v0);
                hc[lane + 32] = add4(hc[lane + 32], r.v1);
                hc[lane + 64] = add4(hc[lane + 64], r.v2);
                hc[lane + 96] = add4(hc[lane + 96], r.v3);
            }
        }

        // prefetch a(t+1)
        if (t + 1 < HW) {
            int pn = t + 1, pxn = pn / WWD, pyn = pn - pxn * WWD;
            int fx = (mode & 2) ? (HH - 1 - pxn) : pxn;
            int fy = (mode & 1) ? (WWD - 1 - pyn) : pyn;
            asmem[(par ^ 1) * CH + tid] = __ldg(Ab + (size_t)(fx * WWD + fy) * CH + tid);
        }
        __syncthreads();   // S1: scr ready

        // assemble h(t), replicated
        float h = hrecv + scr[tid] + scr[CH + tid] + scr[2 * CH + tid];
        hvec[tid] = h;
        if (rank == (t & 7)) Hc[(size_t)t * CH + tid] = h;
        __syncthreads();   // S2: hvec ready

        // matvec: my 64 rows of G(t) = Wh rows . h(t), packed f32x2;
        // all-gather into gbuf[t&3] via 64-bit DSMEM stores.
        {
            const float4* hv4 = (const float4*)hvec;
            float4 h0 = hv4[lane],      h1 = hv4[lane + 32];
            float4 h2 = hv4[lane + 64], h3 = hv4[lane + 96];
            unsigned long long hp[8];
            hp[0] = pack2(h0.x, h0.y); hp[1] = pack2(h0.z, h0.w);
            hp[2] = pack2(h1.x, h1.y); hp[3] = pack2(h1.z, h1.w);
            hp[4] = pack2(h2.x, h2.y); hp[5] = pack2(h2.z, h2.w);
            hp[6] = pack2(h3.x, h3.y); hp[7] = pack2(h3.z, h3.w);
            unsigned long long q0 = 0, q1 = 0, q2 = 0, q3 = 0;
#pragma unroll
            for (int j = 0; j < 8; j++) {
                q0 = fma2(wp[0][j], hp[j], q0);
                q1 = fma2(wp[1][j], hp[j], q1);
                q2 = fma2(wp[2][j], hp[j], q2);
                q3 = fma2(wp[3][j], hp[j], q3);
            }
            float v0 = warp_sum(unpack_sum(q0));
            float v1 = warp_sum(unpack_sum(q1));
            float v2 = warp_sum(unpack_sum(q2));
            float v3 = warp_sum(unpack_sum(q3));
            if (lane < 2) {
                unsigned long long pv = (lane == 0) ? pack2(v0, v1) : pack2(v2, v3);
                uint32_t la = sbase + OFF_GBUF +
                              (uint32_t)(((t & 3) * CH + R + 2 * lane) * 4);
#pragma unroll
                for (int d = 0; d < 8; d++) st_cluster_u64(la, (uint32_t)d, pv);
            }
        }
        CLUSTER_ARRIVE();   // release: gbuf rows + ship
    }
    CLUSTER_WAIT();         // close final generation
}

// ---------------------------------------------------------------------------
// Fused epilogue: Y = Wo @ (sum_m Hv) + 4*b_out, then channel softmax -> out
// ---------------------------------------------------------------------------
__global__ __launch_bounds__(NTHR) void epilogue_kernel(
    const float* __restrict__ Wo, const float* __restrict__ b_out,
    float* __restrict__ out) {
    __shared__ float hs[4 * 520];
    __shared__ float os[4 * 512];
    __shared__ float red[16];
    const int tid = threadIdx.x;
    const int wid = tid >> 5, lane = tid & 31;
    const int b   = blockIdx.x / 49;
    const int p0  = (blockIdx.x % 49) * 4;
#pragma unroll
    for (int j = 0; j < 4; j++) {
        float s0 = g_Hv[((size_t)(0 + b) * HW + p0 + j) * CH + tid];
        float s1 = g_Hv[((size_t)(2 + b) * HW + p0 + j) * CH + tid];
        float s2 = g_Hv[((size_t)(4 + b) * HW + p0 + j) * CH + tid];
        float s3 = g_Hv[((size_t)(6 + b) * HW + p0 + j) * CH + tid];
        hs[j * 520 + tid] = (s0 + s1) + (s2 + s3);
    }
    __syncthreads();

    float4 xv[4][4];
#pragma unroll
    for (int j = 0; j < 4; j++)
#pragma unroll
        for (int kk = 0; kk < 4; kk++)
            xv[j][kk] = *(const float4*)(hs + j * 520 + 4 * lane + 128 * kk);

    for (int g = 0; g < 16; g++) {
        const int r0 = wid * 32 + g * 2;
        float4 w0[4], w1[4];
#pragma unroll
        for (int kk = 0; kk < 4; kk++) {
            w0[kk] = *(const float4*)(Wo + (size_t)r0 * CH + 4 * lane + 128 * kk);
            w1[kk] = *(const float4*)(Wo + (size_t)(r0 + 1) * CH + 4 * lane + 128 * kk);
        }
        float d0[4], d1[4];
#pragma unroll
        for (int j = 0; j < 4; j++) {
            float s0 = 0.f, s1 = 0.f;
#pragma unroll
            for (int kk = 0; kk < 4; kk++) {
                s0 += dot4(w0[kk], xv[j][kk]);
                s1 += dot4(w1[kk], xv[j][kk]);
            }
            d0[j] = warp_sum(s0);
            d1[j] = warp_sum(s1);
        }
        if (lane < 8) {
            int rr = lane >> 2, j = lane & 3;
            os[j * 512 + r0 + rr] = rr ? d1[j] : d0[j];
        }
    }
    __syncthreads();

    float bo = 4.f * b_out[tid];
#pragma unroll
    for (int j = 0; j < 4; j++) {
        float acc = os[j * 512 + tid] + bo;
        float m = warp_max(acc);
        if (lane == 0) red[wid] = m;
        __syncthreads();
        float mm = red[0];
#pragma unroll
        for (int k = 1; k < 16; k++) mm = fmaxf(mm, red[k]);
        float e = __expf(acc - mm);
        __syncthreads();
        float s = warp_sum(e);
        if (lane == 0) red[wid] = s;
        __syncthreads();
        float ss = 0.f;
#pragma unroll
        for (int k = 0; k < 16; k++) ss += red[k];
        out[((size_t)b * CH + tid) * HW + p0 + j] = e / ss;
        __syncthreads();
    }
}

extern "C" void kernel_launch(void* const* d_in, const int* in_sizes, int n_in,
                              void* d_out, int out_size) {
    const float* input = (const float*)d_in[0];
    const float* Wx    = (const float*)d_in[1];
    const float* Wh    = (const float*)d_in[2];
    const float* b_in  = (const float*)d_in[3];
    const float* Wo    = (const float*)d_in[4];
    const float* b_out = (const float*)d_in[5];
    float* out = (float*)d_out;
    (void)in_sizes; (void)n_in; (void)out_size;

    cudaFuncSetAttribute(scan_kernel,
                         cudaFuncAttributeMaxDynamicSharedMemorySize, SMEM_SZ);

    prologue_kernel<<<98, NTHR>>>(input, Wx, b_in);
    scan_kernel<<<NCHAIN * CLUS, NTHR, SMEM_SZ>>>(Wh);
    epilogue_kernel<<<98, NTHR>>>(Wo, b_out, out);
}